// round 14
// baseline (speedup 1.0000x reference)
#include <cuda_runtime.h>
#include <cstdint>
#include <cstddef>

#define N_TOK 4096
#define HDIM  1024
#define NE    8
#define CAP   1536

// ---------------- scratch (static device globals: no allocation) ----------------
__device__ float g_zpart[(size_t)N_TOK * 4];      // per-token importance dot partials
__device__ float g_lpart[(size_t)8 * N_TOK * NE]; // per-tile expert-logit partials
__device__ float g_p0[N_TOK], g_p1[N_TOK];
__device__ int   g_e0[N_TOK], g_e1[N_TOK];
__device__ unsigned char g_mask[N_TOK];
__device__ int   g_idx_i[N_TOK], g_idx_u[N_TOK];
__device__ int   g_cnt[2];
__device__ float g_part[64 * 16];

// zeroing split (R8/R10-proven): output region 25,165,824 float4 total
#define ZA_F4 9830400
#define ZC_F4 (25165824 - ZA_F4)

// ---------------- packed f32x2 helpers ----------------
static __device__ __forceinline__ void fma2(unsigned long long& d,
                                            unsigned long long a,
                                            unsigned long long b) {
    asm("fma.rn.f32x2 %0, %1, %2, %0;" : "+l"(d) : "l"(a), "l"(b));
}
static __device__ __forceinline__ float2 unpack2(unsigned long long v) {
    float2 r;
    asm("mov.b64 {%0, %1}, %2;" : "=f"(r.x), "=f"(r.y) : "l"(v));
    return r;
}

// ---------------- gemmA: X@wi1 -> relu -> dot(wi2) partials ------------------------
// A stored PRE-DUPLICATED; fragments read as LDS.128 (2 dup rows per load, no MOVs).
__global__ __launch_bounds__(256, 2)
void gemmA_kernel(const float* __restrict__ x,
                  const float* __restrict__ wi1, const float* __restrict__ bi1,
                  const float* __restrict__ wi2,
                  float4* __restrict__ zero_base) {
    const int bx = blockIdx.x;
    if (bx >= 128) {
        const int z = bx - 128;
        const float4 zz = make_float4(0.f, 0.f, 0.f, 0.f);
        for (size_t i = (size_t)z * 256 + threadIdx.x; i < (size_t)ZA_F4; i += (size_t)64 * 256)
            zero_base[i] = zz;
        return;
    }
    __shared__ __align__(16) float As[2][8][256];
    __shared__ __align__(16) float Bs[2][8][128];

    const int ncol0 = (bx & 3) * 128;
    const int m0    = (bx >> 2) * 128;
    const int tid   = threadIdx.x;
    const int arow = tid >> 1,  acol = (tid & 1) * 4;
    const int brow = tid >> 5,  bcol = (tid & 31) * 4;
    const float* Ap = x   + (size_t)(m0 + arow) * HDIM + acol;
    const float* Bp = wi1 + (size_t)brow * 512 + ncol0 + bcol;
    const int trow = (tid >> 4) * 8;
    const int tcol = (tid & 15) * 8;

    float4 a_ld = *(const float4*)Ap;
    float4 b_ld = *(const float4*)Bp;
    *(float2*)&As[0][acol + 0][2 * arow] = make_float2(a_ld.x, a_ld.x);
    *(float2*)&As[0][acol + 1][2 * arow] = make_float2(a_ld.y, a_ld.y);
    *(float2*)&As[0][acol + 2][2 * arow] = make_float2(a_ld.z, a_ld.z);
    *(float2*)&As[0][acol + 3][2 * arow] = make_float2(a_ld.w, a_ld.w);
    *(float4*)&Bs[0][brow][bcol] = b_ld;
    __syncthreads();

    unsigned long long acc[8][4];
#pragma unroll
    for (int i = 0; i < 8; i++)
#pragma unroll
        for (int j = 0; j < 4; j++) acc[i][j] = 0ull;

    for (int kt = 0; kt < 128; kt++) {
        const int cur = kt & 1;
        float4 a_n, b_n;
        if (kt < 127) {
            a_n = *(const float4*)(Ap + (kt + 1) * 8);
            b_n = *(const float4*)(Bp + (size_t)(kt + 1) * 8 * 512);
        }
#pragma unroll
        for (int k = 0; k < 8; k++) {
            const ulonglong2 aq0 = *(const ulonglong2*)&As[cur][k][2 * trow];
            const ulonglong2 aq1 = *(const ulonglong2*)&As[cur][k][2 * trow + 4];
            const ulonglong2 aq2 = *(const ulonglong2*)&As[cur][k][2 * trow + 8];
            const ulonglong2 aq3 = *(const ulonglong2*)&As[cur][k][2 * trow + 12];
            const unsigned long long aa[8] = {aq0.x, aq0.y, aq1.x, aq1.y,
                                              aq2.x, aq2.y, aq3.x, aq3.y};
            ulonglong2 bq0 = *(const ulonglong2*)&Bs[cur][k][tcol];
            ulonglong2 bq1 = *(const ulonglong2*)&Bs[cur][k][tcol + 4];
            const unsigned long long bb0 = bq0.x, bb1 = bq0.y, bb2 = bq1.x, bb3 = bq1.y;
#pragma unroll
            for (int i = 0; i < 8; i++) {
                fma2(acc[i][0], aa[i], bb0);
                fma2(acc[i][1], aa[i], bb1);
                fma2(acc[i][2], aa[i], bb2);
                fma2(acc[i][3], aa[i], bb3);
            }
        }
        if (kt < 127) {
            const int nxt = cur ^ 1;
            *(float2*)&As[nxt][acol + 0][2 * arow] = make_float2(a_n.x, a_n.x);
            *(float2*)&As[nxt][acol + 1][2 * arow] = make_float2(a_n.y, a_n.y);
            *(float2*)&As[nxt][acol + 2][2 * arow] = make_float2(a_n.z, a_n.z);
            *(float2*)&As[nxt][acol + 3][2 * arow] = make_float2(a_n.w, a_n.w);
            *(float4*)&Bs[nxt][brow][bcol] = b_n;
            __syncthreads();
        }
    }

    float w[8];
#pragma unroll
    for (int jj = 0; jj < 8; jj++) w[jj] = wi2[ncol0 + tcol + jj];
    float zp[8];
#pragma unroll
    for (int i = 0; i < 8; i++) {
        float s = 0.0f;
#pragma unroll
        for (int j = 0; j < 4; j++) {
            float2 v = unpack2(acc[i][j]);
            v.x = fmaxf(v.x + bi1[ncol0 + tcol + 2 * j],     0.0f);
            v.y = fmaxf(v.y + bi1[ncol0 + tcol + 2 * j + 1], 0.0f);
            s = fmaf(v.x, w[2 * j], s);
            s = fmaf(v.y, w[2 * j + 1], s);
        }
        zp[i] = s;
    }
#pragma unroll
    for (int off = 8; off > 0; off >>= 1)
#pragma unroll
        for (int i = 0; i < 8; i++) zp[i] += __shfl_xor_sync(0xffffffffu, zp[i], off);
    if ((tid & 15) == 0) {
#pragma unroll
        for (int i = 0; i < 8; i++)
            g_zpart[(size_t)(m0 + trow + i) * 4 + (ncol0 >> 7)] = zp[i];
    }
}

// ---------------- gate + compact (fused, single block; proven) ---------------------
__global__ void gate_compact_kernel(const float* __restrict__ bi2,
                                    float* __restrict__ out_imp) {
    __shared__ int wcnt_i[32], wcnt_u[32], wpre_i[32], wpre_u[32];
    __shared__ int base_i, base_u;
    const int tid = threadIdx.x, lane = tid & 31, warp = tid >> 5;
    if (tid == 0) { base_i = 0; base_u = 0; }
    __syncthreads();
    for (int c = 0; c < 4; c++) {
        const int t = c * 1024 + tid;
        const float4 zp = *(const float4*)&g_zpart[(size_t)t * 4];
        const float z = ((zp.x + zp.y) + zp.z) + zp.w + bi2[0];
        const float sig = 1.0f / (1.0f + expf(-z));
        const int m = (sig > 0.5f) ? 1 : 0;
        out_imp[t] = sig;
        g_mask[t] = (unsigned char)m;

        const unsigned bi = __ballot_sync(0xffffffffu, m);
        const unsigned lt = (1u << lane) - 1u;
        if (lane == 0) { wcnt_i[warp] = __popc(bi); wcnt_u[warp] = 32 - __popc(bi); }
        __syncthreads();
        if (tid == 0) {
            int si = base_i, su = base_u;
            for (int w = 0; w < 32; w++) {
                wpre_i[w] = si; si += wcnt_i[w];
                wpre_u[w] = su; su += wcnt_u[w];
            }
            base_i = si; base_u = su;
        }
        __syncthreads();
        if (m) g_idx_i[wpre_i[warp] + __popc(bi & lt)] = t;
        else   g_idx_u[wpre_u[warp] + __popc(~bi & lt)] = t;
        __syncthreads();
    }
    if (tid == 0) { g_cnt[0] = base_i; g_cnt[1] = base_u; }
}

// ---------------- gemmC: gathered router GEMM -> per-tile expert-logit partials ----
__global__ __launch_bounds__(256, 2)
void gemmC_kernel(const float* __restrict__ x,
                  const float* __restrict__ wr1, const float* __restrict__ br1,
                  const float* __restrict__ wu1, const float* __restrict__ bu1,
                  const float* __restrict__ wr2, const float* __restrict__ wu2,
                  float4* __restrict__ zero_base) {
    const int ci = g_cnt[0], cu = g_cnt[1];
    const int ti = (ci + 127) >> 7;
    const int tu = (cu + 127) >> 7;
    const int nc = ti + tu;
    const int bid = blockIdx.x;
    if (bid >= 8 * nc) {
        const int z  = bid - 8 * nc;
        const int nz = 296 - 8 * nc;
        const float4 zz = make_float4(0.f, 0.f, 0.f, 0.f);
        for (size_t i = (size_t)z * 256 + threadIdx.x; i < (size_t)ZC_F4; i += (size_t)nz * 256)
            zero_base[(size_t)ZA_F4 + i] = zz;
        return;
    }
    const int rt = bid >> 3;
    const float* W; const float* bias; const float* W2; const int* list; int base, cnt;
    if (rt < ti) { W = wr1; bias = br1; W2 = wr2; list = g_idx_i; base = rt << 7;        cnt = ci; }
    else         { W = wu1; bias = bu1; W2 = wu2; list = g_idx_u; base = (rt - ti) << 7; cnt = cu; }

    __shared__ __align__(16) float As[2][8][256];
    __shared__ __align__(16) float Bs[2][8][128];
    __shared__ int s_tok[128];

    const int ncol0 = (bid & 7) * 128;
    const int tid   = threadIdx.x;
    if (tid < 128) {
        const int r = base + tid;
        s_tok[tid] = (r < cnt) ? list[r] : -1;
    }
    __syncthreads();

    const int arow = tid >> 1,  acol = (tid & 1) * 4;
    const int brow = tid >> 5,  bcol = (tid & 31) * 4;
    const int tokA = s_tok[arow];
    const float* Ap = x + (size_t)(tokA < 0 ? 0 : tokA) * HDIM + acol;
    const float* Bp = W + (size_t)brow * 1024 + ncol0 + bcol;
    const int trow = (tid >> 4) * 8;
    const int tcol = (tid & 15) * 8;

    float4 a_ld = *(const float4*)Ap;
    float4 b_ld = *(const float4*)Bp;
    *(float2*)&As[0][acol + 0][2 * arow] = make_float2(a_ld.x, a_ld.x);
    *(float2*)&As[0][acol + 1][2 * arow] = make_float2(a_ld.y, a_ld.y);
    *(float2*)&As[0][acol + 2][2 * arow] = make_float2(a_ld.z, a_ld.z);
    *(float2*)&As[0][acol + 3][2 * arow] = make_float2(a_ld.w, a_ld.w);
    *(float4*)&Bs[0][brow][bcol] = b_ld;
    __syncthreads();

    unsigned long long acc[8][4];
#pragma unroll
    for (int i = 0; i < 8; i++)
#pragma unroll
        for (int j = 0; j < 4; j++) acc[i][j] = 0ull;

    for (int kt = 0; kt < 128; kt++) {
        const int cur = kt & 1;
        float4 a_n, b_n;
        if (kt < 127) {
            a_n = *(const float4*)(Ap + (kt + 1) * 8);
            b_n = *(const float4*)(Bp + (size_t)(kt + 1) * 8 * 1024);
        }
#pragma unroll
        for (int k = 0; k < 8; k++) {
            const ulonglong2 aq0 = *(const ulonglong2*)&As[cur][k][2 * trow];
            const ulonglong2 aq1 = *(const ulonglong2*)&As[cur][k][2 * trow + 4];
            const ulonglong2 aq2 = *(const ulonglong2*)&As[cur][k][2 * trow + 8];
            const ulonglong2 aq3 = *(const ulonglong2*)&As[cur][k][2 * trow + 12];
            const unsigned long long aa[8] = {aq0.x, aq0.y, aq1.x, aq1.y,
                                              aq2.x, aq2.y, aq3.x, aq3.y};
            ulonglong2 bq0 = *(const ulonglong2*)&Bs[cur][k][tcol];
            ulonglong2 bq1 = *(const ulonglong2*)&Bs[cur][k][tcol + 4];
            const unsigned long long bb0 = bq0.x, bb1 = bq0.y, bb2 = bq1.x, bb3 = bq1.y;
#pragma unroll
            for (int i = 0; i < 8; i++) {
                fma2(acc[i][0], aa[i], bb0);
                fma2(acc[i][1], aa[i], bb1);
                fma2(acc[i][2], aa[i], bb2);
                fma2(acc[i][3], aa[i], bb3);
            }
        }
        if (kt < 127) {
            const int nxt = cur ^ 1;
            *(float2*)&As[nxt][acol + 0][2 * arow] = make_float2(a_n.x, a_n.x);
            *(float2*)&As[nxt][acol + 1][2 * arow] = make_float2(a_n.y, a_n.y);
            *(float2*)&As[nxt][acol + 2][2 * arow] = make_float2(a_n.z, a_n.z);
            *(float2*)&As[nxt][acol + 3][2 * arow] = make_float2(a_n.w, a_n.w);
            *(float4*)&Bs[nxt][brow][bcol] = b_n;
            __syncthreads();
        }
    }

    // ---- epilogue: stage W2 slice to smem, contract, 16-lane reduce, store --------
    __syncthreads();
    float* sW = &As[0][0][0];                        // [128 cols][8 experts] = 4KB
    {
        const float4* src = (const float4*)(W2 + (size_t)ncol0 * NE);
        float4* dst = (float4*)sW;
        dst[tid] = src[tid];
    }
    __syncthreads();

    const int tile = ncol0 >> 7;
#pragma unroll
    for (int i = 0; i < 8; i++) {
        float le[NE];
#pragma unroll
        for (int e = 0; e < NE; e++) le[e] = 0.0f;
#pragma unroll
        for (int j = 0; j < 4; j++) {
            float2 v = unpack2(acc[i][j]);
            v.x = fmaxf(v.x + bias[ncol0 + tcol + 2 * j],     0.0f);
            v.y = fmaxf(v.y + bias[ncol0 + tcol + 2 * j + 1], 0.0f);
            const float* w0 = sW + (tcol + 2 * j) * NE;
            const float* w1 = w0 + NE;
#pragma unroll
            for (int e = 0; e < NE; e++) {
                le[e] = fmaf(v.x, w0[e], le[e]);
                le[e] = fmaf(v.y, w1[e], le[e]);
            }
        }
#pragma unroll
        for (int off = 8; off > 0; off >>= 1)
#pragma unroll
            for (int e = 0; e < NE; e++) le[e] += __shfl_xor_sync(0xffffffffu, le[e], off);
        if ((tid & 15) == 0) {
            const int tok = s_tok[trow + i];
            if (tok >= 0) {
                float* dst = g_lpart + ((size_t)tile * N_TOK + tok) * NE;
                *(float4*)dst       = make_float4(le[0], le[1], le[2], le[3]);
                *(float4*)(dst + 4) = make_float4(le[4], le[5], le[6], le[7]);
            }
        }
    }
}

// ---------------- routing_lite: 64 blocks x 64 threads (R13-measured 9.5us) --------
__global__ void routing_lite_kernel(const float* __restrict__ br2,
                                    const float* __restrict__ bu2,
                                    float* __restrict__ out_probs) {
    __shared__ float sm[64][16];
    const int tid = threadIdx.x;
    const int t = blockIdx.x * 64 + tid;

    float l[NE];
#pragma unroll
    for (int e = 0; e < NE; e++) l[e] = 0.0f;
#pragma unroll
    for (int tile = 0; tile < 8; tile++) {
        const float* p = g_lpart + ((size_t)tile * N_TOK + t) * NE;
        const float4 p0 = *(const float4*)p;
        const float4 p1 = *(const float4*)(p + 4);
        l[0] += p0.x; l[1] += p0.y; l[2] += p0.z; l[3] += p0.w;
        l[4] += p1.x; l[5] += p1.y; l[6] += p1.z; l[7] += p1.w;
    }
    const bool m = g_mask[t] != 0;
    const float* b2 = m ? br2 : bu2;
    float pr[NE];
    float mx = -1e30f;
#pragma unroll
    for (int e = 0; e < NE; e++) { l[e] += b2[e]; mx = fmaxf(mx, l[e]); }
    float sum = 0.0f;
#pragma unroll
    for (int e = 0; e < NE; e++) { pr[e] = expf(l[e] - mx); sum += pr[e]; }
    const float inv = 1.0f / sum;
    const float mf = m ? 1.0f : 0.0f;
#pragma unroll
    for (int e = 0; e < NE; e++) {
        pr[e] *= inv;
        out_probs[(size_t)t * NE + e] = pr[e];
        sm[tid][e]      = pr[e];
        sm[tid][NE + e] = pr[e] * mf;
    }
    int e0 = 0; float p0v = pr[0];
#pragma unroll
    for (int e = 1; e < NE; e++) if (pr[e] > p0v) { p0v = pr[e]; e0 = e; }
    int e1 = -1; float p1v = -1.0f;
#pragma unroll
    for (int e = 0; e < NE; e++) if (e != e0 && pr[e] > p1v) { p1v = pr[e]; e1 = e; }
    const float sn = p0v + p1v;
    g_e0[t] = e0; g_e1[t] = e1;
    g_p0[t] = p0v / sn; g_p1[t] = p1v / sn;

    __syncthreads();
    for (int s = 32; s > 0; s >>= 1) {
        if (tid < s)
#pragma unroll
            for (int v = 0; v < 16; v++) sm[tid][v] += sm[tid + s][v];
        __syncthreads();
    }
    if (tid < 16) g_part[blockIdx.x * 16 + tid] = sm[0][tid];
}

// ---------------- dispatch (block 0) + aux loss (block 1), merged ------------------
__global__ void dispatch_aux_kernel(float* __restrict__ disp, float* __restrict__ comb,
                                    float* __restrict__ out_aux) {
    const int tid = threadIdx.x;
    if (blockIdx.x == 0) {
        __shared__ int base[NE];
        __shared__ int whist[32][NE];
        __shared__ int wpref[32][NE];
        const int lane = tid & 31, warp = tid >> 5;
        if (tid < NE) base[tid] = 0;
        __syncthreads();
        for (int chunk = 0; chunk < 8; chunk++) {
            const int i = chunk * 1024 + tid;
            const int k = i >> 12;
            const int t = i & (N_TOK - 1);
            const int e   = (k == 0) ? g_e0[t] : g_e1[t];
            const float p = (k == 0) ? g_p0[t] : g_p1[t];

            if (lane < NE) whist[warp][lane] = 0;
            __syncwarp();
            const unsigned mm  = __match_any_sync(0xffffffffu, e);
            const unsigned blo = mm & ((1u << lane) - 1u);
            const int rank = __popc(blo);
            if (blo == 0u) whist[warp][e] = __popc(mm);
            __syncthreads();

            if (tid < NE) {
                int s = base[tid];
                for (int w = 0; w < 32; w++) { wpref[w][tid] = s; s += whist[w][tid]; }
                base[tid] = s;
            }
            __syncthreads();

            const int pos = wpref[warp][e] + rank;
            if (pos < CAP) {
                const size_t idx = ((size_t)t * NE + e) * CAP + pos;
                disp[idx] = 1.0f;
                comb[idx] = p;
            }
            __syncthreads();
        }
    } else {
        __shared__ float S[16];
        if (tid < 16) {
            float s = 0.0f;
            for (int b = 0; b < 64; b++) s += g_part[b * 16 + tid];
            S[tid] = s;
        }
        __syncthreads();
        if (tid == 0) {
            float ent = 0.0f;
#pragma unroll
            for (int e = 0; e < NE; e++) {
                const float r = S[e] / (float)N_TOK;
                ent += r * logf(r * 8.0f + 1e-9f);
            }
            float tot = 0.0f;
            float SI[NE];
#pragma unroll
            for (int e = 0; e < NE; e++) { SI[e] = S[NE + e] + 1e-9f; tot += SI[e]; }
            float ie = 0.0f;
#pragma unroll
            for (int e = 0; e < NE; e++) {
                const float ip = SI[e] / tot;
                ie -= ip * logf(ip + 1e-9f);
            }
            out_aux[0] = ent - 0.1f * (ie / logf(8.0f));
        }
    }
}

// ---------------- launch -----------------------------------------------------------
extern "C" void kernel_launch(void* const* d_in, const int* in_sizes, int n_in,
                              void* d_out, int out_size) {
    const float* x   = (const float*)d_in[0];
    const float* wi1 = (const float*)d_in[1];
    const float* bi1 = (const float*)d_in[2];
    const float* wi2 = (const float*)d_in[3];
    const float* bi2 = (const float*)d_in[4];
    const float* wr1 = (const float*)d_in[5];
    const float* br1 = (const float*)d_in[6];
    const float* wr2 = (const float*)d_in[7];
    const float* br2 = (const float*)d_in[8];
    const float* wu1 = (const float*)d_in[9];
    const float* bu1 = (const float*)d_in[10];
    const float* wu2 = (const float*)d_in[11];
    const float* bu2 = (const float*)d_in[12];

    float* out   = (float*)d_out;
    float* disp  = out;                                   // [4096, 8, 1536]
    float* comb  = disp + (size_t)N_TOK * NE * CAP;       // [4096, 8, 1536]
    float* probs = comb + (size_t)N_TOK * NE * CAP;       // [4096, 8]
    float* aux   = probs + (size_t)N_TOK * NE;            // [1]
    float* imp   = aux + 1;                               // [4096]

    gemmA_kernel<<<192, 256>>>(x, wi1, bi1, wi2, (float4*)disp);
    gate_compact_kernel<<<1, 1024>>>(bi2, imp);
    gemmC_kernel<<<296, 256>>>(x, wr1, br1, wu1, bu1, wr2, wu2, (float4*)disp);
    routing_lite_kernel<<<64, 64>>>(br2, bu2, probs);
    dispatch_aux_kernel<<<2, 1024>>>(disp, comb, aux);
}

// round 15
// speedup vs baseline: 1.1978x; 1.1978x over previous
#include <cuda_runtime.h>
#include <cstdint>
#include <cstddef>

#define N_TOK 4096
#define HDIM  1024
#define NE    8
#define CAP   1536

// ---------------- scratch (static device globals: no allocation) ----------------
__device__ float g_zpart[(size_t)N_TOK * 4];      // per-token importance dot partials
__device__ float g_lpart[(size_t)8 * N_TOK * NE]; // per-tile expert-logit partials
__device__ float g_p0[N_TOK], g_p1[N_TOK];
__device__ int   g_e0[N_TOK], g_e1[N_TOK];
__device__ unsigned char g_mask[N_TOK];
__device__ int   g_idx_i[N_TOK], g_idx_u[N_TOK];
__device__ int   g_cnt[2];
__device__ float g_part[64 * 16];
__device__ int   g_ctr;                           // gemmA completion counter (self-resetting)

// zeroing split (R8/R10-proven): output region 25,165,824 float4 total
#define ZA_F4 9830400
#define ZC_F4 (25165824 - ZA_F4)

// ---------------- packed f32x2 helpers ----------------
static __device__ __forceinline__ void fma2(unsigned long long& d,
                                            unsigned long long a,
                                            unsigned long long b) {
    asm("fma.rn.f32x2 %0, %1, %2, %0;" : "+l"(d) : "l"(a), "l"(b));
}
static __device__ __forceinline__ unsigned long long pack2(float x, float y) {
    unsigned long long r;
    asm("mov.b64 %0, {%1, %2};" : "=l"(r) : "f"(x), "f"(y));
    return r;
}
static __device__ __forceinline__ float2 unpack2(unsigned long long v) {
    float2 r;
    asm("mov.b64 {%0, %1}, %2;" : "=f"(r.x), "=f"(r.y) : "l"(v));
    return r;
}

// ---------------- gemmA: X@wi1 -> relu -> dot(wi2) partials + last-CTA gating ------
// Mainloop/epilogue byte-identical to R10/R12 (measured best). The 128th compute CTA
// to finish performs gate + compact inline (saves one launch + gap).
__global__ __launch_bounds__(256, 2)
void gemmA_kernel(const float* __restrict__ x,
                  const float* __restrict__ wi1, const float* __restrict__ bi1,
                  const float* __restrict__ wi2, const float* __restrict__ bi2,
                  float* __restrict__ out_imp,
                  float4* __restrict__ zero_base) {
    const int bx = blockIdx.x;
    const int tid = threadIdx.x;
    if (bx >= 128) {
        const int z = bx - 128;
        const float4 zz = make_float4(0.f, 0.f, 0.f, 0.f);
        for (size_t i = (size_t)z * 256 + tid; i < (size_t)ZA_F4; i += (size_t)64 * 256)
            zero_base[i] = zz;
        return;
    }
    __shared__ __align__(16) float As[2][8][128];
    __shared__ __align__(16) float Bs[2][8][128];

    const int ncol0 = (bx & 3) * 128;
    const int m0    = (bx >> 2) * 128;
    const int arow = tid >> 1,  acol = (tid & 1) * 4;
    const int brow = tid >> 5,  bcol = (tid & 31) * 4;
    const float* Ap = x   + (size_t)(m0 + arow) * HDIM + acol;
    const float* Bp = wi1 + (size_t)brow * 512 + ncol0 + bcol;
    const int trow = (tid >> 4) * 8;
    const int tcol = (tid & 15) * 8;

    float4 a_ld = *(const float4*)Ap;
    float4 b_ld = *(const float4*)Bp;
    As[0][acol + 0][arow] = a_ld.x;
    As[0][acol + 1][arow] = a_ld.y;
    As[0][acol + 2][arow] = a_ld.z;
    As[0][acol + 3][arow] = a_ld.w;
    *(float4*)&Bs[0][brow][bcol] = b_ld;
    __syncthreads();

    unsigned long long acc[8][4];
#pragma unroll
    for (int i = 0; i < 8; i++)
#pragma unroll
        for (int j = 0; j < 4; j++) acc[i][j] = 0ull;

    for (int kt = 0; kt < 128; kt++) {
        const int cur = kt & 1;
        float4 a_n, b_n;
        if (kt < 127) {
            a_n = *(const float4*)(Ap + (kt + 1) * 8);
            b_n = *(const float4*)(Bp + (size_t)(kt + 1) * 8 * 512);
        }
#pragma unroll
        for (int k = 0; k < 8; k++) {
            float4 a0 = *(const float4*)&As[cur][k][trow];
            float4 a1 = *(const float4*)&As[cur][k][trow + 4];
            ulonglong2 bq0 = *(const ulonglong2*)&Bs[cur][k][tcol];
            ulonglong2 bq1 = *(const ulonglong2*)&Bs[cur][k][tcol + 4];
            const unsigned long long bb0 = bq0.x, bb1 = bq0.y, bb2 = bq1.x, bb3 = bq1.y;
            float av[8] = {a0.x, a0.y, a0.z, a0.w, a1.x, a1.y, a1.z, a1.w};
#pragma unroll
            for (int i = 0; i < 8; i++) {
                unsigned long long aa = pack2(av[i], av[i]);
                fma2(acc[i][0], aa, bb0);
                fma2(acc[i][1], aa, bb1);
                fma2(acc[i][2], aa, bb2);
                fma2(acc[i][3], aa, bb3);
            }
        }
        if (kt < 127) {
            const int nxt = cur ^ 1;
            As[nxt][acol + 0][arow] = a_n.x;
            As[nxt][acol + 1][arow] = a_n.y;
            As[nxt][acol + 2][arow] = a_n.z;
            As[nxt][acol + 3][arow] = a_n.w;
            *(float4*)&Bs[nxt][brow][bcol] = b_n;
            __syncthreads();
        }
    }

    // epilogue: bias + relu + dot(wi2), 16-lane shuffle reduce (R10-proven)
    float w[8];
#pragma unroll
    for (int jj = 0; jj < 8; jj++) w[jj] = wi2[ncol0 + tcol + jj];
    float zp[8];
#pragma unroll
    for (int i = 0; i < 8; i++) {
        float s = 0.0f;
#pragma unroll
        for (int j = 0; j < 4; j++) {
            float2 v = unpack2(acc[i][j]);
            v.x = fmaxf(v.x + bi1[ncol0 + tcol + 2 * j],     0.0f);
            v.y = fmaxf(v.y + bi1[ncol0 + tcol + 2 * j + 1], 0.0f);
            s = fmaf(v.x, w[2 * j], s);
            s = fmaf(v.y, w[2 * j + 1], s);
        }
        zp[i] = s;
    }
#pragma unroll
    for (int off = 8; off > 0; off >>= 1)
#pragma unroll
        for (int i = 0; i < 8; i++) zp[i] += __shfl_xor_sync(0xffffffffu, zp[i], off);
    if ((tid & 15) == 0) {
#pragma unroll
        for (int i = 0; i < 8; i++)
            g_zpart[(size_t)(m0 + trow + i) * 4 + (ncol0 >> 7)] = zp[i];
    }

    // ---- last-CTA gate + compact (threadfence + counter; counter self-resets) ----
    __threadfence();
    __shared__ int s_last;
    __syncthreads();
    if (tid == 0) s_last = (atomicAdd(&g_ctr, 1) == 127) ? 1 : 0;
    __syncthreads();
    if (!s_last) return;

    __shared__ int wcnt_i[8], wcnt_u[8], wpre_i[8], wpre_u[8];
    __shared__ int base_i, base_u;
    const int lane = tid & 31, warp = tid >> 5;
    if (tid == 0) { base_i = 0; base_u = 0; }
    __syncthreads();
    for (int c = 0; c < 16; c++) {
        const int t = c * 256 + tid;
        const float4 zq = *(const float4*)&g_zpart[(size_t)t * 4];
        const float z = ((zq.x + zq.y) + zq.z) + zq.w + bi2[0];
        const float sig = 1.0f / (1.0f + expf(-z));
        const int m = (sig > 0.5f) ? 1 : 0;
        out_imp[t] = sig;
        g_mask[t] = (unsigned char)m;

        const unsigned bi = __ballot_sync(0xffffffffu, m);
        const unsigned lt = (1u << lane) - 1u;
        if (lane == 0) { wcnt_i[warp] = __popc(bi); wcnt_u[warp] = 32 - __popc(bi); }
        __syncthreads();
        if (tid == 0) {
            int si = base_i, su = base_u;
            for (int ww = 0; ww < 8; ww++) {
                wpre_i[ww] = si; si += wcnt_i[ww];
                wpre_u[ww] = su; su += wcnt_u[ww];
            }
            base_i = si; base_u = su;
        }
        __syncthreads();
        if (m) g_idx_i[wpre_i[warp] + __popc(bi & lt)] = t;
        else   g_idx_u[wpre_u[warp] + __popc(~bi & lt)] = t;
        __syncthreads();
    }
    if (tid == 0) { g_cnt[0] = base_i; g_cnt[1] = base_u; g_ctr = 0; }
}

// ---------------- gemmC: gathered router GEMM -> per-tile expert-logit partials ----
// Mainloop byte-identical to R10/R12; epilogue contracts against selected W2 slice.
__global__ __launch_bounds__(256, 2)
void gemmC_kernel(const float* __restrict__ x,
                  const float* __restrict__ wr1, const float* __restrict__ br1,
                  const float* __restrict__ wu1, const float* __restrict__ bu1,
                  const float* __restrict__ wr2, const float* __restrict__ wu2,
                  float4* __restrict__ zero_base) {
    const int ci = g_cnt[0], cu = g_cnt[1];
    const int ti = (ci + 127) >> 7;
    const int tu = (cu + 127) >> 7;
    const int nc = ti + tu;
    const int bid = blockIdx.x;
    if (bid >= 8 * nc) {
        const int z  = bid - 8 * nc;
        const int nz = 296 - 8 * nc;
        const float4 zz = make_float4(0.f, 0.f, 0.f, 0.f);
        for (size_t i = (size_t)z * 256 + threadIdx.x; i < (size_t)ZC_F4; i += (size_t)nz * 256)
            zero_base[(size_t)ZA_F4 + i] = zz;
        return;
    }
    const int rt = bid >> 3;
    const float* W; const float* bias; const float* W2; const int* list; int base, cnt;
    if (rt < ti) { W = wr1; bias = br1; W2 = wr2; list = g_idx_i; base = rt << 7;        cnt = ci; }
    else         { W = wu1; bias = bu1; W2 = wu2; list = g_idx_u; base = (rt - ti) << 7; cnt = cu; }

    __shared__ __align__(16) float As[2][8][128];
    __shared__ __align__(16) float Bs[2][8][128];
    __shared__ int s_tok[128];

    const int ncol0 = (bid & 7) * 128;
    const int tid   = threadIdx.x;
    if (tid < 128) {
        const int r = base + tid;
        s_tok[tid] = (r < cnt) ? list[r] : -1;
    }
    __syncthreads();

    const int arow = tid >> 1,  acol = (tid & 1) * 4;
    const int brow = tid >> 5,  bcol = (tid & 31) * 4;
    const int tokA = s_tok[arow];
    const float* Ap = x + (size_t)(tokA < 0 ? 0 : tokA) * HDIM + acol;
    const float* Bp = W + (size_t)brow * 1024 + ncol0 + bcol;
    const int trow = (tid >> 4) * 8;
    const int tcol = (tid & 15) * 8;

    float4 a_ld = *(const float4*)Ap;
    float4 b_ld = *(const float4*)Bp;
    As[0][acol + 0][arow] = a_ld.x;
    As[0][acol + 1][arow] = a_ld.y;
    As[0][acol + 2][arow] = a_ld.z;
    As[0][acol + 3][arow] = a_ld.w;
    *(float4*)&Bs[0][brow][bcol] = b_ld;
    __syncthreads();

    unsigned long long acc[8][4];
#pragma unroll
    for (int i = 0; i < 8; i++)
#pragma unroll
        for (int j = 0; j < 4; j++) acc[i][j] = 0ull;

    for (int kt = 0; kt < 128; kt++) {
        const int cur = kt & 1;
        float4 a_n, b_n;
        if (kt < 127) {
            a_n = *(const float4*)(Ap + (kt + 1) * 8);
            b_n = *(const float4*)(Bp + (size_t)(kt + 1) * 8 * 1024);
        }
#pragma unroll
        for (int k = 0; k < 8; k++) {
            float4 a0 = *(const float4*)&As[cur][k][trow];
            float4 a1 = *(const float4*)&As[cur][k][trow + 4];
            ulonglong2 bq0 = *(const ulonglong2*)&Bs[cur][k][tcol];
            ulonglong2 bq1 = *(const ulonglong2*)&Bs[cur][k][tcol + 4];
            const unsigned long long bb0 = bq0.x, bb1 = bq0.y, bb2 = bq1.x, bb3 = bq1.y;
            float av[8] = {a0.x, a0.y, a0.z, a0.w, a1.x, a1.y, a1.z, a1.w};
#pragma unroll
            for (int i = 0; i < 8; i++) {
                unsigned long long aa = pack2(av[i], av[i]);
                fma2(acc[i][0], aa, bb0);
                fma2(acc[i][1], aa, bb1);
                fma2(acc[i][2], aa, bb2);
                fma2(acc[i][3], aa, bb3);
            }
        }
        if (kt < 127) {
            const int nxt = cur ^ 1;
            As[nxt][acol + 0][arow] = a_n.x;
            As[nxt][acol + 1][arow] = a_n.y;
            As[nxt][acol + 2][arow] = a_n.z;
            As[nxt][acol + 3][arow] = a_n.w;
            *(float4*)&Bs[nxt][brow][bcol] = b_n;
            __syncthreads();
        }
    }

    // epilogue: stage W2 slice to smem, contract, 16-lane reduce, store (R12-proven)
    __syncthreads();
    float* sW = &As[0][0][0];                        // [128 cols][8 experts] = 4KB
    {
        const float4* src = (const float4*)(W2 + (size_t)ncol0 * NE);
        float4* dst = (float4*)sW;
        dst[tid] = src[tid];
    }
    __syncthreads();

    const int tile = ncol0 >> 7;
#pragma unroll
    for (int i = 0; i < 8; i++) {
        float le[NE];
#pragma unroll
        for (int e = 0; e < NE; e++) le[e] = 0.0f;
#pragma unroll
        for (int j = 0; j < 4; j++) {
            float2 v = unpack2(acc[i][j]);
            v.x = fmaxf(v.x + bias[ncol0 + tcol + 2 * j],     0.0f);
            v.y = fmaxf(v.y + bias[ncol0 + tcol + 2 * j + 1], 0.0f);
            const float* w0 = sW + (tcol + 2 * j) * NE;
            const float* w1 = w0 + NE;
#pragma unroll
            for (int e = 0; e < NE; e++) {
                le[e] = fmaf(v.x, w0[e], le[e]);
                le[e] = fmaf(v.y, w1[e], le[e]);
            }
        }
#pragma unroll
        for (int off = 8; off > 0; off >>= 1)
#pragma unroll
            for (int e = 0; e < NE; e++) le[e] += __shfl_xor_sync(0xffffffffu, le[e], off);
        if ((tid & 15) == 0) {
            const int tok = s_tok[trow + i];
            if (tok >= 0) {
                float* dst = g_lpart + ((size_t)tile * N_TOK + tok) * NE;
                *(float4*)dst       = make_float4(le[0], le[1], le[2], le[3]);
                *(float4*)(dst + 4) = make_float4(le[4], le[5], le[6], le[7]);
            }
        }
    }
}

// ---------------- routing_lite: 64 blocks x 64 threads (R13-measured 9.5us) --------
__global__ void routing_lite_kernel(const float* __restrict__ br2,
                                    const float* __restrict__ bu2,
                                    float* __restrict__ out_probs) {
    __shared__ float sm[64][16];
    const int tid = threadIdx.x;
    const int t = blockIdx.x * 64 + tid;

    float l[NE];
#pragma unroll
    for (int e = 0; e < NE; e++) l[e] = 0.0f;
#pragma unroll
    for (int tile = 0; tile < 8; tile++) {
        const float* p = g_lpart + ((size_t)tile * N_TOK + t) * NE;
        const float4 p0 = *(const float4*)p;
        const float4 p1 = *(const float4*)(p + 4);
        l[0] += p0.x; l[1] += p0.y; l[2] += p0.z; l[3] += p0.w;
        l[4] += p1.x; l[5] += p1.y; l[6] += p1.z; l[7] += p1.w;
    }
    const bool m = g_mask[t] != 0;
    const float* b2 = m ? br2 : bu2;
    float pr[NE];
    float mx = -1e30f;
#pragma unroll
    for (int e = 0; e < NE; e++) { l[e] += b2[e]; mx = fmaxf(mx, l[e]); }
    float sum = 0.0f;
#pragma unroll
    for (int e = 0; e < NE; e++) { pr[e] = expf(l[e] - mx); sum += pr[e]; }
    const float inv = 1.0f / sum;
    const float mf = m ? 1.0f : 0.0f;
#pragma unroll
    for (int e = 0; e < NE; e++) {
        pr[e] *= inv;
        out_probs[(size_t)t * NE + e] = pr[e];
        sm[tid][e]      = pr[e];
        sm[tid][NE + e] = pr[e] * mf;
    }
    int e0 = 0; float p0v = pr[0];
#pragma unroll
    for (int e = 1; e < NE; e++) if (pr[e] > p0v) { p0v = pr[e]; e0 = e; }
    int e1 = -1; float p1v = -1.0f;
#pragma unroll
    for (int e = 0; e < NE; e++) if (e != e0 && pr[e] > p1v) { p1v = pr[e]; e1 = e; }
    const float sn = p0v + p1v;
    g_e0[t] = e0; g_e1[t] = e1;
    g_p0[t] = p0v / sn; g_p1[t] = p1v / sn;

    __syncthreads();
    for (int s = 32; s > 0; s >>= 1) {
        if (tid < s)
#pragma unroll
            for (int v = 0; v < 16; v++) sm[tid][v] += sm[tid + s][v];
        __syncthreads();
    }
    if (tid < 16) g_part[blockIdx.x * 16 + tid] = sm[0][tid];
}

// ---------------- dispatch (block 0) + aux loss (block 1), merged ------------------
__global__ void dispatch_aux_kernel(float* __restrict__ disp, float* __restrict__ comb,
                                    float* __restrict__ out_aux) {
    const int tid = threadIdx.x;
    if (blockIdx.x == 0) {
        __shared__ int base[NE];
        __shared__ int whist[32][NE];
        __shared__ int wpref[32][NE];
        const int lane = tid & 31, warp = tid >> 5;
        if (tid < NE) base[tid] = 0;
        __syncthreads();
        for (int chunk = 0; chunk < 8; chunk++) {
            const int i = chunk * 1024 + tid;
            const int k = i >> 12;
            const int t = i & (N_TOK - 1);
            const int e   = (k == 0) ? g_e0[t] : g_e1[t];
            const float p = (k == 0) ? g_p0[t] : g_p1[t];

            if (lane < NE) whist[warp][lane] = 0;
            __syncwarp();
            const unsigned mm  = __match_any_sync(0xffffffffu, e);
            const unsigned blo = mm & ((1u << lane) - 1u);
            const int rank = __popc(blo);
            if (blo == 0u) whist[warp][e] = __popc(mm);
            __syncthreads();

            if (tid < NE) {
                int s = base[tid];
                for (int w = 0; w < 32; w++) { wpref[w][tid] = s; s += whist[w][tid]; }
                base[tid] = s;
            }
            __syncthreads();

            const int pos = wpref[warp][e] + rank;
            if (pos < CAP) {
                const size_t idx = ((size_t)t * NE + e) * CAP + pos;
                disp[idx] = 1.0f;
                comb[idx] = p;
            }
            __syncthreads();
        }
    } else {
        __shared__ float S[16];
        if (tid < 16) {
            float s = 0.0f;
            for (int b = 0; b < 64; b++) s += g_part[b * 16 + tid];
            S[tid] = s;
        }
        __syncthreads();
        if (tid == 0) {
            float ent = 0.0f;
#pragma unroll
            for (int e = 0; e < NE; e++) {
                const float r = S[e] / (float)N_TOK;
                ent += r * logf(r * 8.0f + 1e-9f);
            }
            float tot = 0.0f;
            float SI[NE];
#pragma unroll
            for (int e = 0; e < NE; e++) { SI[e] = S[NE + e] + 1e-9f; tot += SI[e]; }
            float ie = 0.0f;
#pragma unroll
            for (int e = 0; e < NE; e++) {
                const float ip = SI[e] / tot;
                ie -= ip * logf(ip + 1e-9f);
            }
            out_aux[0] = ent - 0.1f * (ie / logf(8.0f));
        }
    }
}

// ---------------- launch -----------------------------------------------------------
extern "C" void kernel_launch(void* const* d_in, const int* in_sizes, int n_in,
                              void* d_out, int out_size) {
    const float* x   = (const float*)d_in[0];
    const float* wi1 = (const float*)d_in[1];
    const float* bi1 = (const float*)d_in[2];
    const float* wi2 = (const float*)d_in[3];
    const float* bi2 = (const float*)d_in[4];
    const float* wr1 = (const float*)d_in[5];
    const float* br1 = (const float*)d_in[6];
    const float* wr2 = (const float*)d_in[7];
    const float* br2 = (const float*)d_in[8];
    const float* wu1 = (const float*)d_in[9];
    const float* bu1 = (const float*)d_in[10];
    const float* wu2 = (const float*)d_in[11];
    const float* bu2 = (const float*)d_in[12];

    float* out   = (float*)d_out;
    float* disp  = out;                                   // [4096, 8, 1536]
    float* comb  = disp + (size_t)N_TOK * NE * CAP;       // [4096, 8, 1536]
    float* probs = comb + (size_t)N_TOK * NE * CAP;       // [4096, 8]
    float* aux   = probs + (size_t)N_TOK * NE;            // [1]
    float* imp   = aux + 1;                               // [4096]

    gemmA_kernel<<<192, 256>>>(x, wi1, bi1, wi2, bi2, imp, (float4*)disp);
    gemmC_kernel<<<296, 256>>>(x, wr1, br1, wu1, bu1, wr2, wu2, (float4*)disp);
    routing_lite_kernel<<<64, 64>>>(br2, bu2, probs);
    dispatch_aux_kernel<<<2, 1024>>>(disp, comb, aux);
}

// round 17
// speedup vs baseline: 1.2520x; 1.0453x over previous
#include <cuda_runtime.h>
#include <cstdint>
#include <cstddef>

#define N_TOK 4096
#define HDIM  1024
#define NE    8
#define CAP   1536

// ---------------- scratch (static device globals: no allocation) ----------------
__device__ float g_zpart[(size_t)N_TOK * 4];   // per-token importance dot partials
__device__ float g_hr[(size_t)N_TOK * 1024];   // selected-router hidden
__device__ float g_p0[N_TOK], g_p1[N_TOK];
__device__ int   g_e0[N_TOK], g_e1[N_TOK];
__device__ unsigned char g_mask[N_TOK];
__device__ int   g_idx_i[N_TOK], g_idx_u[N_TOK];
__device__ int   g_cnt[2];
__device__ float g_part[512 * 16];

// zeroing split (R8/R10-proven): output region 25,165,824 float4 total
#define ZA_F4 9830400
#define ZC_F4 (25165824 - ZA_F4)

// ---------------- packed f32x2 helpers ----------------
static __device__ __forceinline__ void fma2(unsigned long long& d,
                                            unsigned long long a,
                                            unsigned long long b) {
    asm("fma.rn.f32x2 %0, %1, %2, %0;" : "+l"(d) : "l"(a), "l"(b));
}
static __device__ __forceinline__ unsigned long long pack2(float x, float y) {
    unsigned long long r;
    asm("mov.b64 %0, {%1, %2};" : "=l"(r) : "f"(x), "f"(y));
    return r;
}
static __device__ __forceinline__ float2 unpack2(unsigned long long v) {
    float2 r;
    asm("mov.b64 {%0, %1}, %2;" : "=f"(r.x), "=f"(r.y) : "l"(v));
    return r;
}

// ---------------- gemmA: X@wi1 -> relu -> dot(wi2) partials (R10-proven) -----------
__global__ __launch_bounds__(256, 2)
void gemmA_kernel(const float* __restrict__ x,
                  const float* __restrict__ wi1, const float* __restrict__ bi1,
                  const float* __restrict__ wi2,
                  float4* __restrict__ zero_base) {
    const int bx = blockIdx.x;
    if (bx >= 128) {
        const int z = bx - 128;
        const float4 zz = make_float4(0.f, 0.f, 0.f, 0.f);
        for (size_t i = (size_t)z * 256 + threadIdx.x; i < (size_t)ZA_F4; i += (size_t)64 * 256)
            zero_base[i] = zz;
        return;
    }
    __shared__ __align__(16) float As[2][8][128];
    __shared__ __align__(16) float Bs[2][8][128];

    const int ncol0 = (bx & 3) * 128;
    const int m0    = (bx >> 2) * 128;
    const int tid   = threadIdx.x;
    const int arow = tid >> 1,  acol = (tid & 1) * 4;
    const int brow = tid >> 5,  bcol = (tid & 31) * 4;
    const float* Ap = x   + (size_t)(m0 + arow) * HDIM + acol;
    const float* Bp = wi1 + (size_t)brow * 512 + ncol0 + bcol;
    const int trow = (tid >> 4) * 8;
    const int tcol = (tid & 15) * 8;

    float4 a_ld = *(const float4*)Ap;
    float4 b_ld = *(const float4*)Bp;
    As[0][acol + 0][arow] = a_ld.x;
    As[0][acol + 1][arow] = a_ld.y;
    As[0][acol + 2][arow] = a_ld.z;
    As[0][acol + 3][arow] = a_ld.w;
    *(float4*)&Bs[0][brow][bcol] = b_ld;
    __syncthreads();

    unsigned long long acc[8][4];
#pragma unroll
    for (int i = 0; i < 8; i++)
#pragma unroll
        for (int j = 0; j < 4; j++) acc[i][j] = 0ull;

    for (int kt = 0; kt < 128; kt++) {
        const int cur = kt & 1;
        float4 a_n, b_n;
        if (kt < 127) {
            a_n = *(const float4*)(Ap + (kt + 1) * 8);
            b_n = *(const float4*)(Bp + (size_t)(kt + 1) * 8 * 512);
        }
#pragma unroll
        for (int k = 0; k < 8; k++) {
            float4 a0 = *(const float4*)&As[cur][k][trow];
            float4 a1 = *(const float4*)&As[cur][k][trow + 4];
            ulonglong2 bq0 = *(const ulonglong2*)&Bs[cur][k][tcol];
            ulonglong2 bq1 = *(const ulonglong2*)&Bs[cur][k][tcol + 4];
            const unsigned long long bb0 = bq0.x, bb1 = bq0.y, bb2 = bq1.x, bb3 = bq1.y;
            float av[8] = {a0.x, a0.y, a0.z, a0.w, a1.x, a1.y, a1.z, a1.w};
#pragma unroll
            for (int i = 0; i < 8; i++) {
                unsigned long long aa = pack2(av[i], av[i]);
                fma2(acc[i][0], aa, bb0);
                fma2(acc[i][1], aa, bb1);
                fma2(acc[i][2], aa, bb2);
                fma2(acc[i][3], aa, bb3);
            }
        }
        if (kt < 127) {
            const int nxt = cur ^ 1;
            As[nxt][acol + 0][arow] = a_n.x;
            As[nxt][acol + 1][arow] = a_n.y;
            As[nxt][acol + 2][arow] = a_n.z;
            As[nxt][acol + 3][arow] = a_n.w;
            *(float4*)&Bs[nxt][brow][bcol] = b_n;
            __syncthreads();
        }
    }

    float w[8];
#pragma unroll
    for (int jj = 0; jj < 8; jj++) w[jj] = wi2[ncol0 + tcol + jj];
    float zp[8];
#pragma unroll
    for (int i = 0; i < 8; i++) {
        float s = 0.0f;
#pragma unroll
        for (int j = 0; j < 4; j++) {
            float2 v = unpack2(acc[i][j]);
            v.x = fmaxf(v.x + bi1[ncol0 + tcol + 2 * j],     0.0f);
            v.y = fmaxf(v.y + bi1[ncol0 + tcol + 2 * j + 1], 0.0f);
            s = fmaf(v.x, w[2 * j], s);
            s = fmaf(v.y, w[2 * j + 1], s);
        }
        zp[i] = s;
    }
#pragma unroll
    for (int off = 8; off > 0; off >>= 1)
#pragma unroll
        for (int i = 0; i < 8; i++) zp[i] += __shfl_xor_sync(0xffffffffu, zp[i], off);
    if ((tid & 15) == 0) {
#pragma unroll
        for (int i = 0; i < 8; i++)
            g_zpart[(size_t)(m0 + trow + i) * 4 + (ncol0 >> 7)] = zp[i];
    }
}

// ---------------- gate + compact (fused, single block; R10-proven) -----------------
__global__ void gate_compact_kernel(const float* __restrict__ bi2,
                                    float* __restrict__ out_imp) {
    __shared__ int wcnt_i[32], wcnt_u[32], wpre_i[32], wpre_u[32];
    __shared__ int base_i, base_u;
    const int tid = threadIdx.x, lane = tid & 31, warp = tid >> 5;
    if (tid == 0) { base_i = 0; base_u = 0; }
    __syncthreads();
    for (int c = 0; c < 4; c++) {
        const int t = c * 1024 + tid;
        const float4 zp = *(const float4*)&g_zpart[(size_t)t * 4];
        const float z = ((zp.x + zp.y) + zp.z) + zp.w + bi2[0];
        const float sig = 1.0f / (1.0f + expf(-z));
        const int m = (sig > 0.5f) ? 1 : 0;
        out_imp[t] = sig;
        g_mask[t] = (unsigned char)m;

        const unsigned bi = __ballot_sync(0xffffffffu, m);
        const unsigned lt = (1u << lane) - 1u;
        if (lane == 0) { wcnt_i[warp] = __popc(bi); wcnt_u[warp] = 32 - __popc(bi); }
        __syncthreads();
        if (tid == 0) {
            int si = base_i, su = base_u;
            for (int w = 0; w < 32; w++) {
                wpre_i[w] = si; si += wcnt_i[w];
                wpre_u[w] = su; su += wcnt_u[w];
            }
            base_i = si; base_u = su;
        }
        __syncthreads();
        if (m) g_idx_i[wpre_i[warp] + __popc(bi & lt)] = t;
        else   g_idx_u[wpre_u[warp] + __popc(~bi & lt)] = t;
        __syncthreads();
    }
    if (tid == 0) { g_cnt[0] = base_i; g_cnt[1] = base_u; }
}

// ---------------- gemmC: gathered router GEMM + zero-ballast CTAs (R10-proven) -----
__global__ __launch_bounds__(256, 2)
void gemmC_kernel(const float* __restrict__ x,
                  const float* __restrict__ wr1, const float* __restrict__ br1,
                  const float* __restrict__ wu1, const float* __restrict__ bu1,
                  float4* __restrict__ zero_base) {
    const int ci = g_cnt[0], cu = g_cnt[1];
    const int ti = (ci + 127) >> 7;
    const int tu = (cu + 127) >> 7;
    const int nc = ti + tu;
    const int bid = blockIdx.x;
    if (bid >= 8 * nc) {
        const int z  = bid - 8 * nc;
        const int nz = 296 - 8 * nc;
        const float4 zz = make_float4(0.f, 0.f, 0.f, 0.f);
        for (size_t i = (size_t)z * 256 + threadIdx.x; i < (size_t)ZC_F4; i += (size_t)nz * 256)
            zero_base[(size_t)ZA_F4 + i] = zz;
        return;
    }
    const int rt = bid >> 3;
    const float* W; const float* bias; const int* list; int base, cnt;
    if (rt < ti) { W = wr1; bias = br1; list = g_idx_i; base = rt << 7;        cnt = ci; }
    else         { W = wu1; bias = bu1; list = g_idx_u; base = (rt - ti) << 7; cnt = cu; }

    __shared__ __align__(16) float As[2][8][128];
    __shared__ __align__(16) float Bs[2][8][128];
    __shared__ int s_tok[128];

    const int ncol0 = (bid & 7) * 128;
    const int tid   = threadIdx.x;
    if (tid < 128) {
        const int r = base + tid;
        s_tok[tid] = (r < cnt) ? list[r] : -1;
    }
    __syncthreads();

    const int arow = tid >> 1,  acol = (tid & 1) * 4;
    const int brow = tid >> 5,  bcol = (tid & 31) * 4;
    const int tokA = s_tok[arow];
    const float* Ap = x + (size_t)(tokA < 0 ? 0 : tokA) * HDIM + acol;
    const float* Bp = W + (size_t)brow * 1024 + ncol0 + bcol;
    const int trow = (tid >> 4) * 8;
    const int tcol = (tid & 15) * 8;

    float4 a_ld = *(const float4*)Ap;
    float4 b_ld = *(const float4*)Bp;
    As[0][acol + 0][arow] = a_ld.x;
    As[0][acol + 1][arow] = a_ld.y;
    As[0][acol + 2][arow] = a_ld.z;
    As[0][acol + 3][arow] = a_ld.w;
    *(float4*)&Bs[0][brow][bcol] = b_ld;
    __syncthreads();

    unsigned long long acc[8][4];
#pragma unroll
    for (int i = 0; i < 8; i++)
#pragma unroll
        for (int j = 0; j < 4; j++) acc[i][j] = 0ull;

    for (int kt = 0; kt < 128; kt++) {
        const int cur = kt & 1;
        float4 a_n, b_n;
        if (kt < 127) {
            a_n = *(const float4*)(Ap + (kt + 1) * 8);
            b_n = *(const float4*)(Bp + (size_t)(kt + 1) * 8 * 1024);
        }
#pragma unroll
        for (int k = 0; k < 8; k++) {
            float4 a0 = *(const float4*)&As[cur][k][trow];
            float4 a1 = *(const float4*)&As[cur][k][trow + 4];
            ulonglong2 bq0 = *(const ulonglong2*)&Bs[cur][k][tcol];
            ulonglong2 bq1 = *(const ulonglong2*)&Bs[cur][k][tcol + 4];
            const unsigned long long bb0 = bq0.x, bb1 = bq0.y, bb2 = bq1.x, bb3 = bq1.y;
            float av[8] = {a0.x, a0.y, a0.z, a0.w, a1.x, a1.y, a1.z, a1.w};
#pragma unroll
            for (int i = 0; i < 8; i++) {
                unsigned long long aa = pack2(av[i], av[i]);
                fma2(acc[i][0], aa, bb0);
                fma2(acc[i][1], aa, bb1);
                fma2(acc[i][2], aa, bb2);
                fma2(acc[i][3], aa, bb3);
            }
        }
        if (kt < 127) {
            const int nxt = cur ^ 1;
            As[nxt][acol + 0][arow] = a_n.x;
            As[nxt][acol + 1][arow] = a_n.y;
            As[nxt][acol + 2][arow] = a_n.z;
            As[nxt][acol + 3][arow] = a_n.w;
            *(float4*)&Bs[nxt][brow][bcol] = b_n;
            __syncthreads();
        }
    }

#pragma unroll
    for (int i = 0; i < 8; i++) {
        const int tok = s_tok[trow + i];
        if (tok < 0) continue;
        float* hr = g_hr + (size_t)tok * 1024 + ncol0 + tcol;
#pragma unroll
        for (int j = 0; j < 4; j++) {
            float2 v = unpack2(acc[i][j]);
            v.x = fmaxf(v.x + bias[ncol0 + tcol + 2 * j],     0.0f);
            v.y = fmaxf(v.y + bias[ncol0 + tcol + 2 * j + 1], 0.0f);
            *(float2*)(hr + 2 * j) = v;
        }
    }
}

// ---------------- routing: second layer + softmax + top-2 + aux partials (R10) -----
__global__ void routing_kernel(const float* __restrict__ wr2, const float* __restrict__ br2,
                               const float* __restrict__ wu2, const float* __restrict__ bu2,
                               float* __restrict__ out_probs) {
    __shared__ float s_aux[8][16];
    const int gt   = (blockIdx.x * blockDim.x + threadIdx.x) >> 5;
    const int lane = threadIdx.x & 31;
    const int warp = threadIdx.x >> 5;
    if (gt < N_TOK) {
        const bool m = g_mask[gt] != 0;
        const float* hs = g_hr + (size_t)gt * 1024;
        const float* W2 = m ? wr2 : wu2;
        const float* b2 = m ? br2 : bu2;
        float acc[NE];
#pragma unroll
        for (int e = 0; e < NE; e++) acc[e] = 0.0f;
        for (int j = lane; j < 1024; j += 32) {
            const float hv = hs[j];
            float4 w0 = *(const float4*)(W2 + (size_t)j * 8);
            float4 w1 = *(const float4*)(W2 + (size_t)j * 8 + 4);
            acc[0] = fmaf(hv, w0.x, acc[0]);
            acc[1] = fmaf(hv, w0.y, acc[1]);
            acc[2] = fmaf(hv, w0.z, acc[2]);
            acc[3] = fmaf(hv, w0.w, acc[3]);
            acc[4] = fmaf(hv, w1.x, acc[4]);
            acc[5] = fmaf(hv, w1.y, acc[5]);
            acc[6] = fmaf(hv, w1.z, acc[6]);
            acc[7] = fmaf(hv, w1.w, acc[7]);
        }
#pragma unroll
        for (int off = 16; off > 0; off >>= 1)
#pragma unroll
            for (int e = 0; e < NE; e++) acc[e] += __shfl_xor_sync(0xffffffffu, acc[e], off);

        if (lane == 0) {
            float l[NE], pr[NE];
            float mx = -1e30f;
#pragma unroll
            for (int e = 0; e < NE; e++) { l[e] = acc[e] + b2[e]; mx = fmaxf(mx, l[e]); }
            float sum = 0.0f;
#pragma unroll
            for (int e = 0; e < NE; e++) { pr[e] = expf(l[e] - mx); sum += pr[e]; }
            const float inv = 1.0f / sum;
            const float mf = m ? 1.0f : 0.0f;
#pragma unroll
            for (int e = 0; e < NE; e++) {
                pr[e] *= inv;
                out_probs[(size_t)gt * NE + e] = pr[e];
                s_aux[warp][e]      = pr[e];
                s_aux[warp][NE + e] = pr[e] * mf;
            }
            int e0 = 0; float p0v = pr[0];
#pragma unroll
            for (int e = 1; e < NE; e++) if (pr[e] > p0v) { p0v = pr[e]; e0 = e; }
            int e1 = -1; float p1v = -1.0f;
#pragma unroll
            for (int e = 0; e < NE; e++) if (e != e0 && pr[e] > p1v) { p1v = pr[e]; e1 = e; }
            const float sn = p0v + p1v;
            g_e0[gt] = e0; g_e1[gt] = e1;
            g_p0[gt] = p0v / sn; g_p1[gt] = p1v / sn;
        }
    }
    __syncthreads();
    if (threadIdx.x < 16) {
        float s = 0.0f;
        for (int w = 0; w < 8; w++) s += s_aux[w][threadIdx.x];
        g_part[(size_t)blockIdx.x * 16 + threadIdx.x] = s;
    }
}

// ---------------- dispatch (block 0, hierarchical 3-barrier scan) + aux (block 1) --
// smem budget: ghist 8K + wsum 1K + wbase 1K + aux sm 16K = 26K (fits 48K static)
__global__ void dispatch_aux_kernel(float* __restrict__ disp, float* __restrict__ comb,
                                    float* __restrict__ out_aux) {
    const int tid = threadIdx.x;
    if (blockIdx.x == 0) {
        // 8192 k-major entries = 256 groups of 32; warp w owns groups [8w, 8w+8).
        __shared__ int ghist[256][NE];   // histograms, converted to prefixes in-place
        __shared__ int wsum[32][NE];     // per-warp totals
        __shared__ int wbase[32][NE];    // exclusive prefix per warp
        const int lane = tid & 31, warp = tid >> 5;

        for (int q = tid; q < 256 * NE; q += 1024) (&ghist[0][0])[q] = 0;
        __syncthreads();

        int re[8]; float rp[8]; int rrank[8];
#pragma unroll
        for (int j = 0; j < 8; j++) {
            const int g = warp * 8 + j;
            const int i = g * 32 + lane;
            const int k = i >> 12;
            const int t = i & (N_TOK - 1);
            re[j] = k ? g_e1[t] : g_e0[t];
            rp[j] = k ? g_p1[t] : g_p0[t];
            const unsigned mm  = __match_any_sync(0xffffffffu, re[j]);
            const unsigned blo = mm & ((1u << lane) - 1u);
            rrank[j] = __popc(blo);
            if (blo == 0u) ghist[g][re[j]] = __popc(mm);
        }
        __syncwarp();
        if (lane < NE) {
            int s = 0;
#pragma unroll
            for (int j = 0; j < 8; j++) s += ghist[warp * 8 + j][lane];
            wsum[warp][lane] = s;
        }
        __syncthreads();
        if (tid < NE) {                          // 32-step serial scan per expert
            int s = 0;
            for (int w = 0; w < 32; w++) { wbase[w][tid] = s; s += wsum[w][tid]; }
        }
        __syncthreads();
        if (lane < NE) {                         // convert ghist -> prefixes in place
            int s = wbase[warp][lane];
#pragma unroll
            for (int j = 0; j < 8; j++) {
                const int h = ghist[warp * 8 + j][lane];
                ghist[warp * 8 + j][lane] = s;
                s += h;
            }
        }
        __syncwarp();
#pragma unroll
        for (int j = 0; j < 8; j++) {
            const int g = warp * 8 + j;
            const int i = g * 32 + lane;
            const int t = i & (N_TOK - 1);
            const int pos = ghist[g][re[j]] + rrank[j];
            if (pos < CAP) {
                const size_t idx = ((size_t)t * NE + re[j]) * CAP + pos;
                disp[idx] = 1.0f;
                comb[idx] = rp[j];
            }
        }
    } else {
        __shared__ float sm[256][16];
        if (tid < 256) {
#pragma unroll
            for (int v = 0; v < 16; v++)
                sm[tid][v] = g_part[(size_t)tid * 16 + v] +
                             g_part[(size_t)(tid + 256) * 16 + v];
        }
        __syncthreads();
        for (int s = 128; s > 0; s >>= 1) {
            if (tid < s)
#pragma unroll
                for (int v = 0; v < 16; v++) sm[tid][v] += sm[tid + s][v];
            __syncthreads();
        }
        if (tid == 0) {
            float ent = 0.0f;
#pragma unroll
            for (int e = 0; e < NE; e++) {
                const float r = sm[0][e] / (float)N_TOK;
                ent += r * logf(r * 8.0f + 1e-9f);
            }
            float tot = 0.0f;
            float SI[NE];
#pragma unroll
            for (int e = 0; e < NE; e++) { SI[e] = sm[0][NE + e] + 1e-9f; tot += SI[e]; }
            float ie = 0.0f;
#pragma unroll
            for (int e = 0; e < NE; e++) {
                const float ip = SI[e] / tot;
                ie -= ip * logf(ip + 1e-9f);
            }
            out_aux[0] = ent - 0.1f * (ie / logf(8.0f));
        }
    }
}

// ---------------- launch -----------------------------------------------------------
extern "C" void kernel_launch(void* const* d_in, const int* in_sizes, int n_in,
                              void* d_out, int out_size) {
    const float* x   = (const float*)d_in[0];
    const float* wi1 = (const float*)d_in[1];
    const float* bi1 = (const float*)d_in[2];
    const float* wi2 = (const float*)d_in[3];
    const float* bi2 = (const float*)d_in[4];
    const float* wr1 = (const float*)d_in[5];
    const float* br1 = (const float*)d_in[6];
    const float* wr2 = (const float*)d_in[7];
    const float* br2 = (const float*)d_in[8];
    const float* wu1 = (const float*)d_in[9];
    const float* bu1 = (const float*)d_in[10];
    const float* wu2 = (const float*)d_in[11];
    const float* bu2 = (const float*)d_in[12];

    float* out   = (float*)d_out;
    float* disp  = out;                                   // [4096, 8, 1536]
    float* comb  = disp + (size_t)N_TOK * NE * CAP;       // [4096, 8, 1536]
    float* probs = comb + (size_t)N_TOK * NE * CAP;       // [4096, 8]
    float* aux   = probs + (size_t)N_TOK * NE;            // [1]
    float* imp   = aux + 1;                               // [4096]

    gemmA_kernel<<<192, 256>>>(x, wi1, bi1, wi2, (float4*)disp);
    gate_compact_kernel<<<1, 1024>>>(bi2, imp);
    gemmC_kernel<<<296, 256>>>(x, wr1, br1, wu1, bu1, (float4*)disp);
    routing_kernel<<<512, 256>>>(wr2, br2, wu2, bu2, probs);
    dispatch_aux_kernel<<<2, 1024>>>(disp, comb, aux);
}